// round 15
// baseline (speedup 1.0000x reference)
#include <cuda_runtime.h>
#include <cuda_fp16.h>
#include <math.h>

#define EPSV 1e-5f

static const int BATCH = 4;
static const int CCH   = 512;
static const int NSP   = 4096;   // H*W

// ---------------- scratch (device globals; no runtime allocation) ----------------
__device__ float  g_xn [(size_t)4 * 512 * 4096];
__device__ float  g_v  [(size_t)4 * 512 * 4096];   // h buffer (style block, fp32)
__device__ float  g_o  [(size_t)4 * 512 * 4096];   // attn out + split-K partials
__device__ float  g_cf [(size_t)4 * 512 * 4096];
__device__ float  g_sf [(size_t)4 * 512 * 4096];
__device__ float  g_attn[(size_t)4 * 4096 * 4096];
__device__ __half g_ah [(size_t)4 * 4096 * 4096];  // fp16 attention weights
__device__ __half g_qh [(size_t)4 * 4096 * 512];   // q transposed [N][C] fp16
__device__ __half g_kh [(size_t)4 * 4096 * 512];   // k transposed [N][C] fp16
__device__ __half g_vh [(size_t)4 * 512 * 4096];   // v fp16 [C][N]
__device__ __half g_fh [(size_t)4 * 512 * 4096];   // f fp16 [C][N]
__device__ __half g_gh [(size_t)4 * 512 * 4096];   // g fp16 [C][N]

// ---------------- helpers ----------------
__device__ __forceinline__ unsigned pack2h(float lo, float hi) {
    unsigned u;
    asm("cvt.rn.f16x2.f32 %0, %1, %2;" : "=r"(u) : "f"(hi), "f"(lo));
    return u;
}

__device__ __forceinline__ void mma16(float* c, const unsigned* a, const unsigned* b) {
    asm volatile(
        "mma.sync.aligned.m16n8k16.row.col.f32.f16.f16.f32 "
        "{%0,%1,%2,%3}, {%4,%5,%6,%7}, {%8,%9}, {%0,%1,%2,%3};"
        : "+f"(c[0]), "+f"(c[1]), "+f"(c[2]), "+f"(c[3])
        : "r"(a[0]), "r"(a[1]), "r"(a[2]), "r"(a[3]), "r"(b[0]), "r"(b[1]));
}

// ---------------- MVN: per-row mean/var normalize (unbiased var, ddof=1) ----------------
__global__ void mvn_kernel(const float* __restrict__ x, float* __restrict__ y, int n) {
    const float* xr = x + (size_t)blockIdx.x * n;
    float*       yr = y + (size_t)blockIdx.x * n;
    int tid = threadIdx.x;
    float s = 0.f, s2 = 0.f;
    for (int i = tid; i < n; i += blockDim.x) {
        float v = xr[i];
        s += v; s2 += v * v;
    }
    __shared__ float sh0[256];
    __shared__ float sh1[256];
    sh0[tid] = s; sh1[tid] = s2;
    __syncthreads();
    for (int o = 128; o > 0; o >>= 1) {
        if (tid < o) { sh0[tid] += sh0[tid + o]; sh1[tid] += sh1[tid + o]; }
        __syncthreads();
    }
    float mean = sh0[0] / (float)n;
    float var  = (sh1[0] - (float)n * mean * mean) / (float)(n - 1);
    float inv  = rsqrtf(var + EPSV);
    for (int i = tid; i < n; i += blockDim.x) {
        yr[i] = (xr[i] - mean) * inv;
    }
}

// ---------------- channel softmax (rows of 512 fp32, in place) ----------------
__global__ void softmax_kernel(float* __restrict__ data, int n) {
    float* r = data + (size_t)blockIdx.x * n;
    int tid = threadIdx.x;
    int per = n / blockDim.x;
    float buf[16];
    __shared__ float sh[256];

    float m = -1e30f;
#pragma unroll 16
    for (int i = 0; i < 16; i++) {
        if (i < per) {
            float v = r[tid + i * blockDim.x];
            buf[i] = v;
            m = fmaxf(m, v);
        }
    }
    sh[tid] = m; __syncthreads();
    for (int o = 128; o > 0; o >>= 1) {
        if (tid < o) sh[tid] = fmaxf(sh[tid], sh[tid + o]);
        __syncthreads();
    }
    float mx = sh[0];
    __syncthreads();

    float s = 0.f;
#pragma unroll 16
    for (int i = 0; i < 16; i++) {
        if (i < per) {
            float e = __expf(buf[i] - mx);
            buf[i] = e;
            s += e;
        }
    }
    sh[tid] = s; __syncthreads();
    for (int o = 128; o > 0; o >>= 1) {
        if (tid < o) sh[tid] += sh[tid + o];
        __syncthreads();
    }
    float inv = 1.f / sh[0];
#pragma unroll 16
    for (int i = 0; i < 16; i++) {
        if (i < per) r[tid + i * blockDim.x] = buf[i] * inv;
    }
}

// ---------------- spatial softmax: fp32 energies in, fp16 weights out ----------------
__global__ void softmaxh_kernel(const float* __restrict__ ein, __half* __restrict__ aout) {
    const float* r = ein + (size_t)blockIdx.x * 4096;
    __half* w = aout + (size_t)blockIdx.x * 4096;
    int tid = threadIdx.x;   // 256, 16 per thread
    float buf[16];
    __shared__ float sh[256];

    float m = -1e30f;
#pragma unroll
    for (int i = 0; i < 16; i++) {
        float v = r[tid + i * 256];
        buf[i] = v;
        m = fmaxf(m, v);
    }
    sh[tid] = m; __syncthreads();
    for (int o = 128; o > 0; o >>= 1) {
        if (tid < o) sh[tid] = fmaxf(sh[tid], sh[tid + o]);
        __syncthreads();
    }
    float mx = sh[0];
    __syncthreads();
    float s = 0.f;
#pragma unroll
    for (int i = 0; i < 16; i++) {
        float e = __expf(buf[i] - mx);
        buf[i] = e;
        s += e;
    }
    sh[tid] = s; __syncthreads();
    for (int o = 128; o > 0; o >>= 1) {
        if (tid < o) sh[tid] += sh[tid + o];
        __syncthreads();
    }
    float inv = 1.f / sh[0];
#pragma unroll
    for (int i = 0; i < 16; i++) {
        w[tid + i * 256] = __float2half_rn(buf[i] * inv);
    }
}

// ---------------- split-K partial reduction: out[b][i] = sum_kc part[b*8+kc][i] ----------------
__global__ void reduce8_kernel(const float* __restrict__ part, float* __restrict__ out) {
    const long long WWv = (long long)512 * 512 / 4;
    long long gid = (long long)blockIdx.x * blockDim.x + threadIdx.x;
    long long b = gid / WWv, i = gid % WWv;
    const float4* p = (const float4*)part + b * 8 * WWv + i;
    float4 a = p[0];
#pragma unroll
    for (int kc = 1; kc < 8; kc++) {
        float4 v = p[(long long)kc * WWv];
        a.x += v.x; a.y += v.y; a.z += v.z; a.w += v.w;
    }
    ((float4*)out)[b * WWv + i] = a;
}

// ---------------- FP16 tensor-core batched GEMM, BK=16, templated paths ----------------
// C[b][m][n] = sum_k A(m,k)*B(k,n) + bias[m] + res[b][m][n]
// AHALF/BHALF: operand is __half, requires K-contiguous (sak==1 / sbk==1).
// OUT: 0 = fp32 row-major C; 1 = fp16 row-major C; 2 = fp16 transposed C[col*M+row].
// nsplit>1: blockIdx.z = b*nsplit + kc (partial C slabs, no bias/res, OUT=0 only).
// Requires M%128==0, N%128==0, K%16==0.
#define RS 132   // row stride in float2 units (128 + 4 pad)
template<int AHALF, int BHALF, int OUT>
__global__ __launch_bounds__(256) void gemm_h(
    const void* __restrict__ Avp, const void* __restrict__ Bvp, void* __restrict__ Cvp,
    long long aBatch, long long sam, long long sak,
    long long bBatch, long long sbk, long long sbn,
    long long cBatch,
    const float* __restrict__ bias,
    const float* __restrict__ res, long long rBatch,
    int M, int N, int K, int nsplit)
{
    const int BM = 128, BK = 16;
    __shared__ float2 As2[4][RS];
    __shared__ float2 Bs2[4][RS];

    int bz = blockIdx.z;
    int kc = 0;
    if (nsplit > 1) { kc = bz % nsplit; bz /= nsplit; }
    long long aBase = (long long)bz * aBatch + (long long)kc * K * sak;
    long long bBase = (long long)bz * bBatch + (long long)kc * K * sbk;
    const float*  Af = (const float*) Avp + aBase;
    const __half* Ah = (const __half*)Avp + aBase;
    const float*  Bf = (const float*) Bvp + bBase;
    const __half* Bh = (const __half*)Bvp + bBase;
    long long cBase = (long long)(bz * nsplit + kc) * cBatch;
    float*  Cf = (float*) Cvp + cBase;
    __half* Ch = (__half*)Cvp + cBase;
    if (res) res += (long long)bz * rBatch;

    int tid  = threadIdx.x;
    int lane = tid & 31;
    int warp = tid >> 5;
    int m0 = blockIdx.y * BM;
    int n0 = blockIdx.x * BM;
    int wm = (warp & 1) * 64;   // 2 warps along M
    int wn = (warp >> 1) * 32;  // 4 warps along N

    bool aK = (sak == 1);
    bool bK = (sbk == 1);

    // ---- loader descriptors ----
    int a_j = 0, a_mm = 0, a_m = 0;
    long long aOff;
    if (aK) { a_j = tid & 7; a_mm = tid >> 3;
              aOff = (long long)(m0 + a_mm) * sam + 2 * a_j; }
    else    { a_m = tid & 127;
              aOff = (long long)(m0 + a_m) + (long long)((tid >> 7) * 8) * sak; }
    int b_j = 0, b_nn = 0, b_n = 0;
    long long bOff;
    if (bK) { b_j = tid & 7; b_nn = tid >> 3;
              bOff = (long long)(n0 + b_nn) * sbn + 2 * b_j; }
    else    { b_n = tid & 127;
              bOff = (long long)(n0 + b_n) + (long long)((tid >> 7) * 8) * sbk; }
    int selA = tid >> 7;
    int selB = tid >> 7;

    // fragment read indices (float2 units) — proven layout
    int r = lane >> 2;
    const unsigned aIdx = (unsigned)((lane & 3) * RS + wm + r);
    const unsigned bIdx = (unsigned)((lane & 3) * RS + wn + r);
    const float2* a2p = &As2[0][0];
    const float2* b2p = &Bs2[0][0];

    float acc[4][4][4];
#pragma unroll
    for (int mt = 0; mt < 4; mt++)
#pragma unroll
        for (int nt = 0; nt < 4; nt++)
#pragma unroll
            for (int i = 0; i < 4; i++) acc[mt][nt][i] = 0.f;

    // register prefetch of tile 0
    float2 pa2[4], pb2[4];
    float  pa[8],  pb[8];
    unsigned pau[4], pbu[4];
    if (AHALF) {
#pragma unroll
        for (int i = 0; i < 4; i++) pau[i] = *(const unsigned*)(Ah + aOff + (long long)(32 * i) * sam);
    } else if (aK) {
#pragma unroll
        for (int i = 0; i < 4; i++) pa2[i] = *(const float2*)(Af + aOff + (long long)(32 * i) * sam);
    } else {
#pragma unroll
        for (int u = 0; u < 8; u++) pa[u] = Af[aOff + (long long)u * sak];
    }
    if (BHALF) {
#pragma unroll
        for (int i = 0; i < 4; i++) pbu[i] = *(const unsigned*)(Bh + bOff + (long long)(32 * i) * sbn);
    } else if (bK) {
#pragma unroll
        for (int i = 0; i < 4; i++) pb2[i] = *(const float2*)(Bf + bOff + (long long)(32 * i) * sbn);
    } else {
#pragma unroll
        for (int u = 0; u < 8; u++) pb[u] = Bf[bOff + (long long)u * sbk];
    }

    for (int k0 = 0; k0 < K; k0 += BK) {
        // ---- stage tile (regs -> smem, f16) ----
        if (AHALF) {
#pragma unroll
            for (int i = 0; i < 4; i++)
                ((unsigned*)&As2[a_j & 3][a_mm + 32 * i])[a_j >> 2] = pau[i];
        } else if (aK) {
#pragma unroll
            for (int i = 0; i < 4; i++)
                ((unsigned*)&As2[a_j & 3][a_mm + 32 * i])[a_j >> 2] = pack2h(pa2[i].x, pa2[i].y);
        } else {
#pragma unroll
            for (int jj = 0; jj < 4; jj++)
                ((unsigned*)&As2[jj][a_m])[selA] = pack2h(pa[2 * jj], pa[2 * jj + 1]);
        }
        if (BHALF) {
#pragma unroll
            for (int i = 0; i < 4; i++)
                ((unsigned*)&Bs2[b_j & 3][b_nn + 32 * i])[b_j >> 2] = pbu[i];
        } else if (bK) {
#pragma unroll
            for (int i = 0; i < 4; i++)
                ((unsigned*)&Bs2[b_j & 3][b_nn + 32 * i])[b_j >> 2] = pack2h(pb2[i].x, pb2[i].y);
        } else {
#pragma unroll
            for (int jj = 0; jj < 4; jj++)
                ((unsigned*)&Bs2[jj][b_n])[selB] = pack2h(pb[2 * jj], pb[2 * jj + 1]);
        }
        __syncthreads();

        // ---- prefetch next tile ----
        aOff += (long long)BK * sak;
        bOff += (long long)BK * sbk;
        if (k0 + BK < K) {
            if (AHALF) {
#pragma unroll
                for (int i = 0; i < 4; i++) pau[i] = *(const unsigned*)(Ah + aOff + (long long)(32 * i) * sam);
            } else if (aK) {
#pragma unroll
                for (int i = 0; i < 4; i++) pa2[i] = *(const float2*)(Af + aOff + (long long)(32 * i) * sam);
            } else {
#pragma unroll
                for (int u = 0; u < 8; u++) pa[u] = Af[aOff + (long long)u * sak];
            }
            if (BHALF) {
#pragma unroll
                for (int i = 0; i < 4; i++) pbu[i] = *(const unsigned*)(Bh + bOff + (long long)(32 * i) * sbn);
            } else if (bK) {
#pragma unroll
                for (int i = 0; i < 4; i++) pb2[i] = *(const float2*)(Bf + bOff + (long long)(32 * i) * sbn);
            } else {
#pragma unroll
                for (int u = 0; u < 8; u++) pb[u] = Bf[bOff + (long long)u * sbk];
            }
        }

        // ---- compute one k16 slice ----
        unsigned af[4][4], bf[4][2];
#pragma unroll
        for (int mt = 0; mt < 4; mt++) {
            float2 lo = a2p[aIdx + mt * 16];
            float2 hi = a2p[aIdx + mt * 16 + 8];
            af[mt][0] = __float_as_uint(lo.x);
            af[mt][1] = __float_as_uint(hi.x);
            af[mt][2] = __float_as_uint(lo.y);
            af[mt][3] = __float_as_uint(hi.y);
        }
#pragma unroll
        for (int nt = 0; nt < 4; nt++) {
            float2 pbv = b2p[bIdx + nt * 8];
            bf[nt][0] = __float_as_uint(pbv.x);
            bf[nt][1] = __float_as_uint(pbv.y);
        }
#pragma unroll
        for (int mt = 0; mt < 4; mt++)
#pragma unroll
            for (int nt = 0; nt < 4; nt++)
                mma16(acc[mt][nt], af[mt], bf[nt]);
        __syncthreads();
    }

    // ---- epilogue ----
#pragma unroll
    for (int mt = 0; mt < 4; mt++) {
        int row = m0 + wm + mt * 16 + (lane >> 2);
        float bi0 = bias ? bias[row]     : 0.f;
        float bi1 = bias ? bias[row + 8] : 0.f;
#pragma unroll
        for (int nt = 0; nt < 4; nt++) {
            int col = n0 + wn + nt * 8 + 2 * (lane & 3);
            float v00 = acc[mt][nt][0] + bi0, v01 = acc[mt][nt][1] + bi0;
            float v10 = acc[mt][nt][2] + bi1, v11 = acc[mt][nt][3] + bi1;
            if (OUT == 0) {
                if (res) {
                    float2 r0 = *(const float2*)(res + (long long)row * N + col);
                    float2 r1 = *(const float2*)(res + (long long)(row + 8) * N + col);
                    v00 += r0.x; v01 += r0.y; v10 += r1.x; v11 += r1.y;
                }
                *(float2*)(Cf + (long long)row * N + col)       = make_float2(v00, v01);
                *(float2*)(Cf + (long long)(row + 8) * N + col) = make_float2(v10, v11);
            } else if (OUT == 1) {
                *(unsigned*)(Ch + (long long)row * N + col)       = pack2h(v00, v01);
                *(unsigned*)(Ch + (long long)(row + 8) * N + col) = pack2h(v10, v11);
            } else {
                Ch[(long long)col * M + row]           = __float2half_rn(v00);
                Ch[(long long)(col + 1) * M + row]     = __float2half_rn(v01);
                Ch[(long long)col * M + row + 8]       = __float2half_rn(v10);
                Ch[(long long)(col + 1) * M + row + 8] = __float2half_rn(v11);
            }
        }
    }
}

// ---------------- orchestration ----------------
extern "C" void kernel_launch(void* const* d_in, const int* in_sizes, int n_in,
                              void* d_out, int out_size) {
    const float* content = (const float*)d_in[0];
    const float* style   = (const float*)d_in[1];
    const float* csa_w   = (const float*)d_in[2];
    const float* csa_b   = (const float*)d_in[3];
    const float* ssa_w   = (const float*)d_in[4];
    const float* ssa_b   = (const float*)d_in[5];
    const float* ca_w    = (const float*)d_in[6];
    const float* ca_b    = (const float*)d_in[7];

    float *xn, *v, *o, *cf, *sf, *attn;
    __half *ah, *qh, *kh, *vh, *fh, *gh;
    cudaGetSymbolAddress((void**)&xn,   g_xn);
    cudaGetSymbolAddress((void**)&v,    g_v);
    cudaGetSymbolAddress((void**)&o,    g_o);
    cudaGetSymbolAddress((void**)&cf,   g_cf);
    cudaGetSymbolAddress((void**)&sf,   g_sf);
    cudaGetSymbolAddress((void**)&attn, g_attn);
    cudaGetSymbolAddress((void**)&ah,   g_ah);
    cudaGetSymbolAddress((void**)&qh,   g_qh);
    cudaGetSymbolAddress((void**)&kh,   g_kh);
    cudaGetSymbolAddress((void**)&vh,   g_vh);
    cudaGetSymbolAddress((void**)&fh,   g_fh);
    cudaGetSymbolAddress((void**)&gh,   g_gh);

    const int B = BATCH, C = CCH, N = NSP;
    const long long CN = (long long)C * N;
    const long long NN = (long long)N * N;
    const long long WW = (long long)C * C;

    dim3 convGrid(N / 128, C / 128, B);          // (32,4,4)
    dim3 enGrid  (N / 128, N / 128, B);          // (32,32,4)
    dim3 chSplitGrid(C / 128, C / 128, B * 8);   // (4,4,32)

    // ================= content self-attention =================
    mvn_kernel<<<B * C, 256>>>(content, xn, N);
    // q,k convs -> transposed fp16 [N][C]
    gemm_h<0,0,2><<<convGrid, 256>>>(csa_w + 0 * WW, xn, qh, 0, C, 1, CN, N, 1, CN, csa_b + 0 * C, nullptr, 0, C, N, C, 1);
    gemm_h<0,0,2><<<convGrid, 256>>>(csa_w + 1 * WW, xn, kh, 0, C, 1, CN, N, 1, CN, csa_b + 1 * C, nullptr, 0, C, N, C, 1);
    // v conv -> fp16 [C][N]
    gemm_h<0,0,1><<<convGrid, 256>>>(csa_w + 2 * WW, content, vh, 0, C, 1, CN, N, 1, CN, csa_b + 2 * C, nullptr, 0, C, N, C, 1);
    // E[i,j] = sum_c qt[i][c] kt[j][c]  (both K-contig fp16)
    gemm_h<1,1,0><<<enGrid, 256>>>(qh, kh, attn, CN, C, 1, CN, 1, C, NN, nullptr, nullptr, 0, N, N, C, 1);
    softmaxh_kernel<<<B * N, 256>>>(attn, ah);
    // O[c,i] = sum_j vh[c][j] attn[i][j]
    gemm_h<1,1,0><<<convGrid, 256>>>(vh, ah, o, CN, N, 1, NN, 1, N, CN, nullptr, nullptr, 0, C, N, N, 1);
    gemm_h<0,0,0><<<convGrid, 256>>>(csa_w + 3 * WW, o, cf, 0, C, 1, CN, N, 1, CN, csa_b + 3 * C, content, CN, C, N, C, 1);

    // ================= style self-attention (channel attention) =================
    mvn_kernel<<<B * C, 256>>>(style, xn, N);
    // f,g convs -> fp16 [C][N]
    gemm_h<0,0,1><<<convGrid, 256>>>(ssa_w + 0 * WW, style, fh, 0, C, 1, CN, N, 1, CN, ssa_b + 0 * C, nullptr, 0, C, N, C, 1);
    gemm_h<0,0,1><<<convGrid, 256>>>(ssa_w + 1 * WW, style, gh, 0, C, 1, CN, N, 1, CN, ssa_b + 1 * C, nullptr, 0, C, N, C, 1);
    // h conv -> fp32 [C][N]
    gemm_h<0,0,0><<<convGrid, 256>>>(ssa_w + 2 * WW, xn, v, 0, C, 1, CN, N, 1, CN, ssa_b + 2 * C, nullptr, 0, C, N, C, 1);
    // E[c,d] = sum_i f[c,i] g[d,i] — split-K x8 (both K-contig fp16)
    gemm_h<1,1,0><<<chSplitGrid, 256>>>(fh, gh, o, CN, N, 1, CN, 1, N, WW, nullptr, nullptr, 0, C, C, N / 8, 8);
    reduce8_kernel<<<(int)(B * WW / 4 / 256), 256>>>(o, attn);
    softmax_kernel<<<B * C, 256>>>(attn, C);
    // O[c,i] = sum_d attn[d,c] h[d,i]
    gemm_h<0,0,0><<<convGrid, 256>>>(attn, v, o, WW, 1, C, CN, N, 1, CN, nullptr, nullptr, 0, C, N, C, 1);
    gemm_h<0,0,0><<<convGrid, 256>>>(ssa_w + 3 * WW, o, sf, 0, C, 1, CN, N, 1, CN, ssa_b + 3 * C, style, CN, C, N, C, 1);

    // ================= cross attention =================
    mvn_kernel<<<B * C, 256>>>(cf, xn, N);
    gemm_h<0,0,2><<<convGrid, 256>>>(ca_w + 0 * WW, xn, qh, 0, C, 1, CN, N, 1, CN, ca_b + 0 * C, nullptr, 0, C, N, C, 1);
    mvn_kernel<<<B * C, 256>>>(sf, xn, N);
    gemm_h<0,0,2><<<convGrid, 256>>>(ca_w + 1 * WW, xn, kh, 0, C, 1, CN, N, 1, CN, ca_b + 1 * C, nullptr, 0, C, N, C, 1);
    gemm_h<0,0,1><<<convGrid, 256>>>(ca_w + 2 * WW, sf, vh, 0, C, 1, CN, N, 1, CN, ca_b + 2 * C, nullptr, 0, C, N, C, 1);
    gemm_h<1,1,0><<<enGrid, 256>>>(qh, kh, attn, CN, C, 1, CN, 1, C, NN, nullptr, nullptr, 0, N, N, C, 1);
    softmaxh_kernel<<<B * N, 256>>>(attn, ah);
    gemm_h<1,1,0><<<convGrid, 256>>>(vh, ah, o, CN, N, 1, NN, 1, N, CN, nullptr, nullptr, 0, C, N, N, 1);
    gemm_h<0,0,0><<<convGrid, 256>>>(ca_w + 3 * WW, o, (float*)d_out, 0, C, 1, CN, N, 1, CN, ca_b + 3 * C, cf, CN, C, N, C, 1);
}

// round 16
// speedup vs baseline: 1.0793x; 1.0793x over previous
#include <cuda_runtime.h>
#include <cuda_fp16.h>
#include <math.h>

#define EPSV 1e-5f

static const int BATCH = 4;
static const int CCH   = 512;
static const int NSP   = 4096;   // H*W

// ---------------- scratch (device globals; no runtime allocation) ----------------
__device__ float  g_xn [(size_t)4 * 512 * 4096];
__device__ float  g_v  [(size_t)4 * 512 * 4096];   // h buffer (style block, fp32)
__device__ float  g_o  [(size_t)4 * 512 * 4096];   // attn out + split-K partials
__device__ float  g_cf [(size_t)4 * 512 * 4096];
__device__ float  g_sf [(size_t)4 * 512 * 4096];
__device__ float  g_attn[(size_t)4 * 4096 * 4096];
__device__ __half g_ah [(size_t)4 * 4096 * 4096];  // fp16 attention weights
__device__ __half g_qh [(size_t)4 * 4096 * 512];   // q transposed [N][C] fp16
__device__ __half g_kh [(size_t)4 * 4096 * 512];   // k transposed [N][C] fp16
__device__ __half g_vh [(size_t)4 * 512 * 4096];   // v fp16 [C][N]
__device__ __half g_fh [(size_t)4 * 512 * 4096];   // f fp16 [C][N]
__device__ __half g_gh [(size_t)4 * 512 * 4096];   // g fp16 [C][N]

// ---------------- helpers ----------------
__device__ __forceinline__ unsigned pack2h(float lo, float hi) {
    unsigned u;
    asm("cvt.rn.f16x2.f32 %0, %1, %2;" : "=r"(u) : "f"(hi), "f"(lo));
    return u;
}

__device__ __forceinline__ void mma16(float* c, const unsigned* a, const unsigned* b) {
    asm volatile(
        "mma.sync.aligned.m16n8k16.row.col.f32.f16.f16.f32 "
        "{%0,%1,%2,%3}, {%4,%5,%6,%7}, {%8,%9}, {%0,%1,%2,%3};"
        : "+f"(c[0]), "+f"(c[1]), "+f"(c[2]), "+f"(c[3])
        : "r"(a[0]), "r"(a[1]), "r"(a[2]), "r"(a[3]), "r"(b[0]), "r"(b[1]));
}

// ---------------- MVN: per-row mean/var normalize (unbiased var, ddof=1) ----------------
__global__ void mvn_kernel(const float* __restrict__ x, float* __restrict__ y, int n) {
    const float* xr = x + (size_t)blockIdx.x * n;
    float*       yr = y + (size_t)blockIdx.x * n;
    int tid = threadIdx.x;
    float s = 0.f, s2 = 0.f;
    for (int i = tid; i < n; i += blockDim.x) {
        float v = xr[i];
        s += v; s2 += v * v;
    }
    __shared__ float sh0[256];
    __shared__ float sh1[256];
    sh0[tid] = s; sh1[tid] = s2;
    __syncthreads();
    for (int o = 128; o > 0; o >>= 1) {
        if (tid < o) { sh0[tid] += sh0[tid + o]; sh1[tid] += sh1[tid + o]; }
        __syncthreads();
    }
    float mean = sh0[0] / (float)n;
    float var  = (sh1[0] - (float)n * mean * mean) / (float)(n - 1);
    float inv  = rsqrtf(var + EPSV);
    for (int i = tid; i < n; i += blockDim.x) {
        yr[i] = (xr[i] - mean) * inv;
    }
}

// ---------------- channel softmax (rows of 512 fp32, in place) ----------------
__global__ void softmax_kernel(float* __restrict__ data, int n) {
    float* r = data + (size_t)blockIdx.x * n;
    int tid = threadIdx.x;
    int per = n / blockDim.x;
    float buf[16];
    __shared__ float sh[256];

    float m = -1e30f;
#pragma unroll 16
    for (int i = 0; i < 16; i++) {
        if (i < per) {
            float v = r[tid + i * blockDim.x];
            buf[i] = v;
            m = fmaxf(m, v);
        }
    }
    sh[tid] = m; __syncthreads();
    for (int o = 128; o > 0; o >>= 1) {
        if (tid < o) sh[tid] = fmaxf(sh[tid], sh[tid + o]);
        __syncthreads();
    }
    float mx = sh[0];
    __syncthreads();

    float s = 0.f;
#pragma unroll 16
    for (int i = 0; i < 16; i++) {
        if (i < per) {
            float e = __expf(buf[i] - mx);
            buf[i] = e;
            s += e;
        }
    }
    sh[tid] = s; __syncthreads();
    for (int o = 128; o > 0; o >>= 1) {
        if (tid < o) sh[tid] += sh[tid + o];
        __syncthreads();
    }
    float inv = 1.f / sh[0];
#pragma unroll 16
    for (int i = 0; i < 16; i++) {
        if (i < per) r[tid + i * blockDim.x] = buf[i] * inv;
    }
}

// ---------------- spatial softmax: fp32 energies in, fp16 weights out ----------------
__global__ void softmaxh_kernel(const float* __restrict__ ein, __half* __restrict__ aout) {
    const float* r = ein + (size_t)blockIdx.x * 4096;
    __half* w = aout + (size_t)blockIdx.x * 4096;
    int tid = threadIdx.x;   // 256, 16 per thread
    float buf[16];
    __shared__ float sh[256];

    float m = -1e30f;
#pragma unroll
    for (int i = 0; i < 16; i++) {
        float v = r[tid + i * 256];
        buf[i] = v;
        m = fmaxf(m, v);
    }
    sh[tid] = m; __syncthreads();
    for (int o = 128; o > 0; o >>= 1) {
        if (tid < o) sh[tid] = fmaxf(sh[tid], sh[tid + o]);
        __syncthreads();
    }
    float mx = sh[0];
    __syncthreads();
    float s = 0.f;
#pragma unroll
    for (int i = 0; i < 16; i++) {
        float e = __expf(buf[i] - mx);
        buf[i] = e;
        s += e;
    }
    sh[tid] = s; __syncthreads();
    for (int o = 128; o > 0; o >>= 1) {
        if (tid < o) sh[tid] += sh[tid + o];
        __syncthreads();
    }
    float inv = 1.f / sh[0];
#pragma unroll
    for (int i = 0; i < 16; i++) {
        w[tid + i * 256] = __float2half_rn(buf[i] * inv);
    }
}

// ---------------- split-K partial reduction: out[b][i] = sum_kc part[b*8+kc][i] ----------------
__global__ void reduce8_kernel(const float* __restrict__ part, float* __restrict__ out) {
    const long long WWv = (long long)512 * 512 / 4;
    long long gid = (long long)blockIdx.x * blockDim.x + threadIdx.x;
    long long b = gid / WWv, i = gid % WWv;
    const float4* p = (const float4*)part + b * 8 * WWv + i;
    float4 a = p[0];
#pragma unroll
    for (int kc = 1; kc < 8; kc++) {
        float4 v = p[(long long)kc * WWv];
        a.x += v.x; a.y += v.y; a.z += v.z; a.w += v.w;
    }
    ((float4*)out)[b * WWv + i] = a;
}

// ---------------- FP16 tensor-core batched GEMM, BK=16, templated paths ----------------
// C[b][m][n] = sum_k A(m,k)*B(k,n) + bias[m] + res[b][m][n]
// AHALF/BHALF: operand is __half, requires K-contiguous (sak==1 / sbk==1).
// OUT: 0 = fp32 row-major C; 1 = fp16 row-major C; 2 = fp16 transposed C[col*M+row].
// nsplit>1: blockIdx.z = b*nsplit + kc (partial C slabs, no bias/res, OUT=0 only).
// Requires M%128==0, N%128==0, K%16==0.
#define RS 132   // row stride in float2 units (128 + 4 pad)
template<int AHALF, int BHALF, int OUT>
__global__ __launch_bounds__(256, 2) void gemm_h(
    const void* __restrict__ Avp, const void* __restrict__ Bvp, void* __restrict__ Cvp,
    long long aBatch, long long sam, long long sak,
    long long bBatch, long long sbk, long long sbn,
    long long cBatch,
    const float* __restrict__ bias,
    const float* __restrict__ res, long long rBatch,
    int M, int N, int K, int nsplit)
{
    const int BM = 128, BK = 16;
    __shared__ float2 As2[4][RS];
    __shared__ float2 Bs2[4][RS];

    int bz = blockIdx.z;
    int kc = 0;
    if (nsplit > 1) { kc = bz % nsplit; bz /= nsplit; }
    const float*  Af = (const float*) Avp + (long long)bz * aBatch + (long long)kc * K * sak;
    const __half* Ah = (const __half*)Avp + (long long)bz * aBatch + (long long)kc * K * sak;
    const float*  Bf = (const float*) Bvp + (long long)bz * bBatch + (long long)kc * K * sbk;
    const __half* Bh = (const __half*)Bvp + (long long)bz * bBatch + (long long)kc * K * sbk;
    const long long cBase = (long long)(bz * nsplit + kc) * cBatch;
    if (res) res += (long long)bz * rBatch;

    int tid  = threadIdx.x;
    int lane = tid & 31;
    int warp = tid >> 5;
    int m0 = blockIdx.y * BM;
    int n0 = blockIdx.x * BM;
    int wm = (warp & 1) * 64;   // 2 warps along M
    int wn = (warp >> 1) * 32;  // 4 warps along N

    bool aK = (sak == 1);
    bool bK = (sbk == 1);

    // ---- loader descriptors ----
    int a_j = 0, a_mm = 0, a_m = 0;
    long long aOff;
    if (aK) { a_j = tid & 7; a_mm = tid >> 3;
              aOff = (long long)(m0 + a_mm) * sam + 2 * a_j; }
    else    { a_m = tid & 127;
              aOff = (long long)(m0 + a_m) + (long long)((tid >> 7) * 8) * sak; }
    int b_j = 0, b_nn = 0, b_n = 0;
    long long bOff;
    if (bK) { b_j = tid & 7; b_nn = tid >> 3;
              bOff = (long long)(n0 + b_nn) * sbn + 2 * b_j; }
    else    { b_n = tid & 127;
              bOff = (long long)(n0 + b_n) + (long long)((tid >> 7) * 8) * sbk; }
    int selA = tid >> 7;
    int selB = tid >> 7;

    // fragment read indices (float2 units) — proven layout
    int r = lane >> 2;
    const unsigned aIdx = (unsigned)((lane & 3) * RS + wm + r);
    const unsigned bIdx = (unsigned)((lane & 3) * RS + wn + r);
    const float2* a2p = &As2[0][0];
    const float2* b2p = &Bs2[0][0];

    float acc[4][4][4];
#pragma unroll
    for (int mt = 0; mt < 4; mt++)
#pragma unroll
        for (int nt = 0; nt < 4; nt++)
#pragma unroll
            for (int i = 0; i < 4; i++) acc[mt][nt][i] = 0.f;

    // register prefetch of tile 0
    float2 pa2[4], pb2[4];
    float  pa[8],  pb[8];
    unsigned pau[4], pbu[4];
    if (AHALF) {
#pragma unroll
        for (int i = 0; i < 4; i++) pau[i] = *(const unsigned*)(Ah + aOff + (long long)(32 * i) * sam);
    } else if (aK) {
#pragma unroll
        for (int i = 0; i < 4; i++) pa2[i] = *(const float2*)(Af + aOff + (long long)(32 * i) * sam);
    } else {
#pragma unroll
        for (int u = 0; u < 8; u++) pa[u] = Af[aOff + (long long)u * sak];
    }
    if (BHALF) {
#pragma unroll
        for (int i = 0; i < 4; i++) pbu[i] = *(const unsigned*)(Bh + bOff + (long long)(32 * i) * sbn);
    } else if (bK) {
#pragma unroll
        for (int i = 0; i < 4; i++) pb2[i] = *(const float2*)(Bf + bOff + (long long)(32 * i) * sbn);
    } else {
#pragma unroll
        for (int u = 0; u < 8; u++) pb[u] = Bf[bOff + (long long)u * sbk];
    }

    for (int k0 = 0; k0 < K; k0 += BK) {
        // ---- stage tile (regs -> smem, f16) ----
        if (AHALF) {
#pragma unroll
            for (int i = 0; i < 4; i++)
                ((unsigned*)&As2[a_j & 3][a_mm + 32 * i])[a_j >> 2] = pau[i];
        } else if (aK) {
#pragma unroll
            for (int i = 0; i < 4; i++)
                ((unsigned*)&As2[a_j & 3][a_mm + 32 * i])[a_j >> 2] = pack2h(pa2[i].x, pa2[i].y);
        } else {
#pragma unroll
            for (int jj = 0; jj < 4; jj++)
                ((unsigned*)&As2[jj][a_m])[selA] = pack2h(pa[2 * jj], pa[2 * jj + 1]);
        }
        if (BHALF) {
#pragma unroll
            for (int i = 0; i < 4; i++)
                ((unsigned*)&Bs2[b_j & 3][b_nn + 32 * i])[b_j >> 2] = pbu[i];
        } else if (bK) {
#pragma unroll
            for (int i = 0; i < 4; i++)
                ((unsigned*)&Bs2[b_j & 3][b_nn + 32 * i])[b_j >> 2] = pack2h(pb2[i].x, pb2[i].y);
        } else {
#pragma unroll
            for (int jj = 0; jj < 4; jj++)
                ((unsigned*)&Bs2[jj][b_n])[selB] = pack2h(pb[2 * jj], pb[2 * jj + 1]);
        }
        __syncthreads();

        // ---- prefetch next tile ----
        aOff += (long long)BK * sak;
        bOff += (long long)BK * sbk;
        if (k0 + BK < K) {
            if (AHALF) {
#pragma unroll
                for (int i = 0; i < 4; i++) pau[i] = *(const unsigned*)(Ah + aOff + (long long)(32 * i) * sam);
            } else if (aK) {
#pragma unroll
                for (int i = 0; i < 4; i++) pa2[i] = *(const float2*)(Af + aOff + (long long)(32 * i) * sam);
            } else {
#pragma unroll
                for (int u = 0; u < 8; u++) pa[u] = Af[aOff + (long long)u * sak];
            }
            if (BHALF) {
#pragma unroll
                for (int i = 0; i < 4; i++) pbu[i] = *(const unsigned*)(Bh + bOff + (long long)(32 * i) * sbn);
            } else if (bK) {
#pragma unroll
                for (int i = 0; i < 4; i++) pb2[i] = *(const float2*)(Bf + bOff + (long long)(32 * i) * sbn);
            } else {
#pragma unroll
                for (int u = 0; u < 8; u++) pb[u] = Bf[bOff + (long long)u * sbk];
            }
        }

        // ---- compute one k16 slice ----
        unsigned af[4][4], bf[4][2];
#pragma unroll
        for (int mt = 0; mt < 4; mt++) {
            float2 lo = a2p[aIdx + mt * 16];
            float2 hi = a2p[aIdx + mt * 16 + 8];
            af[mt][0] = __float_as_uint(lo.x);
            af[mt][1] = __float_as_uint(hi.x);
            af[mt][2] = __float_as_uint(lo.y);
            af[mt][3] = __float_as_uint(hi.y);
        }
#pragma unroll
        for (int nt = 0; nt < 4; nt++) {
            float2 pbv = b2p[bIdx + nt * 8];
            bf[nt][0] = __float_as_uint(pbv.x);
            bf[nt][1] = __float_as_uint(pbv.y);
        }
#pragma unroll
        for (int mt = 0; mt < 4; mt++)
#pragma unroll
            for (int nt = 0; nt < 4; nt++)
                mma16(acc[mt][nt], af[mt], bf[nt]);
        __syncthreads();
    }

    // ---- epilogue (C pointers materialized here, not in prologue) ----
    float*  Cf = (float*) Cvp + cBase;
    __half* Ch = (__half*)Cvp + cBase;
#pragma unroll
    for (int mt = 0; mt < 4; mt++) {
        int row = m0 + wm + mt * 16 + (lane >> 2);
        float bi0 = bias ? bias[row]     : 0.f;
        float bi1 = bias ? bias[row + 8] : 0.f;
#pragma unroll
        for (int nt = 0; nt < 4; nt++) {
            int col = n0 + wn + nt * 8 + 2 * (lane & 3);
            float v00 = acc[mt][nt][0] + bi0, v01 = acc[mt][nt][1] + bi0;
            float v10 = acc[mt][nt][2] + bi1, v11 = acc[mt][nt][3] + bi1;
            if (OUT == 0) {
                if (res) {
                    float2 r0 = *(const float2*)(res + (long long)row * N + col);
                    float2 r1 = *(const float2*)(res + (long long)(row + 8) * N + col);
                    v00 += r0.x; v01 += r0.y; v10 += r1.x; v11 += r1.y;
                }
                *(float2*)(Cf + (long long)row * N + col)       = make_float2(v00, v01);
                *(float2*)(Cf + (long long)(row + 8) * N + col) = make_float2(v10, v11);
            } else if (OUT == 1) {
                *(unsigned*)(Ch + (long long)row * N + col)       = pack2h(v00, v01);
                *(unsigned*)(Ch + (long long)(row + 8) * N + col) = pack2h(v10, v11);
            } else {
                Ch[(long long)col * M + row]           = __float2half_rn(v00);
                Ch[(long long)(col + 1) * M + row]     = __float2half_rn(v01);
                Ch[(long long)col * M + row + 8]       = __float2half_rn(v10);
                Ch[(long long)(col + 1) * M + row + 8] = __float2half_rn(v11);
            }
        }
    }
}

// ---------------- orchestration ----------------
extern "C" void kernel_launch(void* const* d_in, const int* in_sizes, int n_in,
                              void* d_out, int out_size) {
    const float* content = (const float*)d_in[0];
    const float* style   = (const float*)d_in[1];
    const float* csa_w   = (const float*)d_in[2];
    const float* csa_b   = (const float*)d_in[3];
    const float* ssa_w   = (const float*)d_in[4];
    const float* ssa_b   = (const float*)d_in[5];
    const float* ca_w    = (const float*)d_in[6];
    const float* ca_b    = (const float*)d_in[7];

    float *xn, *v, *o, *cf, *sf, *attn;
    __half *ah, *qh, *kh, *vh, *fh, *gh;
    cudaGetSymbolAddress((void**)&xn,   g_xn);
    cudaGetSymbolAddress((void**)&v,    g_v);
    cudaGetSymbolAddress((void**)&o,    g_o);
    cudaGetSymbolAddress((void**)&cf,   g_cf);
    cudaGetSymbolAddress((void**)&sf,   g_sf);
    cudaGetSymbolAddress((void**)&attn, g_attn);
    cudaGetSymbolAddress((void**)&ah,   g_ah);
    cudaGetSymbolAddress((void**)&qh,   g_qh);
    cudaGetSymbolAddress((void**)&kh,   g_kh);
    cudaGetSymbolAddress((void**)&vh,   g_vh);
    cudaGetSymbolAddress((void**)&fh,   g_fh);
    cudaGetSymbolAddress((void**)&gh,   g_gh);

    const int B = BATCH, C = CCH, N = NSP;
    const long long CN = (long long)C * N;
    const long long NN = (long long)N * N;
    const long long WW = (long long)C * C;

    dim3 convGrid(N / 128, C / 128, B);          // (32,4,4)
    dim3 enGrid  (N / 128, N / 128, B);          // (32,32,4)
    dim3 chSplitGrid(C / 128, C / 128, B * 8);   // (4,4,32)

    // ================= content self-attention =================
    mvn_kernel<<<B * C, 256>>>(content, xn, N);
    // q,k convs -> transposed fp16 [N][C]
    gemm_h<0,0,2><<<convGrid, 256>>>(csa_w + 0 * WW, xn, qh, 0, C, 1, CN, N, 1, CN, csa_b + 0 * C, nullptr, 0, C, N, C, 1);
    gemm_h<0,0,2><<<convGrid, 256>>>(csa_w + 1 * WW, xn, kh, 0, C, 1, CN, N, 1, CN, csa_b + 1 * C, nullptr, 0, C, N, C, 1);
    // v conv -> fp16 [C][N]
    gemm_h<0,0,1><<<convGrid, 256>>>(csa_w + 2 * WW, content, vh, 0, C, 1, CN, N, 1, CN, csa_b + 2 * C, nullptr, 0, C, N, C, 1);
    // E[i,j] = sum_c qt[i][c] kt[j][c]  (both K-contig fp16)
    gemm_h<1,1,0><<<enGrid, 256>>>(qh, kh, attn, CN, C, 1, CN, 1, C, NN, nullptr, nullptr, 0, N, N, C, 1);
    softmaxh_kernel<<<B * N, 256>>>(attn, ah);
    // O[c,i] = sum_j vh[c][j] attn[i][j]
    gemm_h<1,1,0><<<convGrid, 256>>>(vh, ah, o, CN, N, 1, NN, 1, N, CN, nullptr, nullptr, 0, C, N, N, 1);
    gemm_h<0,0,0><<<convGrid, 256>>>(csa_w + 3 * WW, o, cf, 0, C, 1, CN, N, 1, CN, csa_b + 3 * C, content, CN, C, N, C, 1);

    // ================= style self-attention (channel attention) =================
    mvn_kernel<<<B * C, 256>>>(style, xn, N);
    // f,g convs -> fp16 [C][N]
    gemm_h<0,0,1><<<convGrid, 256>>>(ssa_w + 0 * WW, style, fh, 0, C, 1, CN, N, 1, CN, ssa_b + 0 * C, nullptr, 0, C, N, C, 1);
    gemm_h<0,0,1><<<convGrid, 256>>>(ssa_w + 1 * WW, style, gh, 0, C, 1, CN, N, 1, CN, ssa_b + 1 * C, nullptr, 0, C, N, C, 1);
    // h conv -> fp32 [C][N]
    gemm_h<0,0,0><<<convGrid, 256>>>(ssa_w + 2 * WW, xn, v, 0, C, 1, CN, N, 1, CN, ssa_b + 2 * C, nullptr, 0, C, N, C, 1);
    // E[c,d] = sum_i f[c,i] g[d,i] — split-K x8 (both K-contig fp16)
    gemm_h<1,1,0><<<chSplitGrid, 256>>>(fh, gh, o, CN, N, 1, CN, 1, N, WW, nullptr, nullptr, 0, C, C, N / 8, 8);
    reduce8_kernel<<<(int)(B * WW / 4 / 256), 256>>>(o, attn);
    softmax_kernel<<<B * C, 256>>>(attn, C);
    // O[c,i] = sum_d attn[d,c] h[d,i]
    gemm_h<0,0,0><<<convGrid, 256>>>(attn, v, o, WW, 1, C, CN, N, 1, CN, nullptr, nullptr, 0, C, N, C, 1);
    gemm_h<0,0,0><<<convGrid, 256>>>(ssa_w + 3 * WW, o, sf, 0, C, 1, CN, N, 1, CN, ssa_b + 3 * C, style, CN, C, N, C, 1);

    // ================= cross attention =================
    mvn_kernel<<<B * C, 256>>>(cf, xn, N);
    gemm_h<0,0,2><<<convGrid, 256>>>(ca_w + 0 * WW, xn, qh, 0, C, 1, CN, N, 1, CN, ca_b + 0 * C, nullptr, 0, C, N, C, 1);
    mvn_kernel<<<B * C, 256>>>(sf, xn, N);
    gemm_h<0,0,2><<<convGrid, 256>>>(ca_w + 1 * WW, xn, kh, 0, C, 1, CN, N, 1, CN, ca_b + 1 * C, nullptr, 0, C, N, C, 1);
    gemm_h<0,0,1><<<convGrid, 256>>>(ca_w + 2 * WW, sf, vh, 0, C, 1, CN, N, 1, CN, ca_b + 2 * C, nullptr, 0, C, N, C, 1);
    gemm_h<1,1,0><<<enGrid, 256>>>(qh, kh, attn, CN, C, 1, CN, 1, C, NN, nullptr, nullptr, 0, N, N, C, 1);
    softmaxh_kernel<<<B * N, 256>>>(attn, ah);
    gemm_h<1,1,0><<<convGrid, 256>>>(vh, ah, o, CN, N, 1, NN, 1, N, CN, nullptr, nullptr, 0, C, N, N, 1);
    gemm_h<0,0,0><<<convGrid, 256>>>(ca_w + 3 * WW, o, (float*)d_out, 0, C, 1, CN, N, 1, CN, ca_b + 3 * C, cf, CN, C, N, C, 1);
}